// round 15
// baseline (speedup 1.0000x reference)
#include <cuda_runtime.h>
#include <math.h>

// Fixed shapes: x (4, 32, 8192, 64) fp32, token_positions = arange(8192)
#define SEQ        8192
#define LOG2_THETA 13.2877123795494489f // log2(10000), fp32
#define N8_TOTAL   (4 * 32 * SEQ * 8)   // 8,388,608 float8 chunks (64 floats/row = 8 chunks)

// Blackwell 256-bit vector ld/st (ld.global.v8.b32 — sm_100+, never emitted by
// ptxas from C++). One thread = one 32-byte chunk = 4 rotation pairs.
// Per-warp L1tex queue load: 1 LDG.256 = 8 lines — identical to R9's two
// front-batched LDG.128 (the R10 16-line depth that regressed is avoided).
// Half the load/store instruction count of R9 per byte; trig doubles but
// stays hidden under the load latency (R9 issue was only 35.9%).
__global__ void __launch_bounds__(256, 6)
rope_v8(const float* __restrict__ x, float* __restrict__ out,
        const int* __restrict__ pos) {
    int i  = blockIdx.x * 256 + threadIdx.x;    // float8 index, 0..N8_TOTAL-1
    int j2 = i & 7;                             // which 8-float chunk in the row
    int p  = (i >> 3) & (SEQ - 1);              // seq position

    // ---- 256-bit load FIRST: DRAM latency covers the 4 sincosf below ----
    const float* xp = x + ((size_t)i << 3);
    float a0, a1, a2, a3, a4, a5, a6, a7;
    asm volatile("ld.global.v8.b32 {%0,%1,%2,%3,%4,%5,%6,%7}, [%8];"
        : "=f"(a0), "=f"(a1), "=f"(a2), "=f"(a3),
          "=f"(a4), "=f"(a5), "=f"(a6), "=f"(a7)
        : "l"(xp));

    // ---- Inline trig for pairs k = 4*j2 .. 4*j2+3 ----
    float posf = (float)__ldg(&pos[p]);
    int   k0   = j2 * 4;
    float c0, s0, c1, s1, c2, s2, c3, s3;
    sincosf(posf * exp2f(-(float)(k0 + 0) * (LOG2_THETA / 32.0f)), &s0, &c0);
    sincosf(posf * exp2f(-(float)(k0 + 1) * (LOG2_THETA / 32.0f)), &s1, &c1);
    sincosf(posf * exp2f(-(float)(k0 + 2) * (LOG2_THETA / 32.0f)), &s2, &c2);
    sincosf(posf * exp2f(-(float)(k0 + 3) * (LOG2_THETA / 32.0f)), &s3, &c3);

    // ---- Rotate 4 even/odd pairs ----
    float o0 = c0 * a0 - s0 * a1,  o1 = s0 * a0 + c0 * a1;
    float o2 = c1 * a2 - s1 * a3,  o3 = s1 * a2 + c1 * a3;
    float o4 = c2 * a4 - s2 * a5,  o5 = s2 * a4 + c2 * a5;
    float o6 = c3 * a6 - s3 * a7,  o7 = s3 * a6 + c3 * a7;

    // ---- 256-bit store ----
    float* op = out + ((size_t)i << 3);
    asm volatile("st.global.v8.b32 [%0], {%1,%2,%3,%4,%5,%6,%7,%8};"
        :: "l"(op),
           "f"(o0), "f"(o1), "f"(o2), "f"(o3),
           "f"(o4), "f"(o5), "f"(o6), "f"(o7)
        : "memory");
}

extern "C" void kernel_launch(void* const* d_in, const int* in_sizes, int n_in,
                              void* d_out, int out_size) {
    const float* x   = (const float*)d_in[0];
    const int*   pos = (const int*)d_in[1];
    float*       out = (float*)d_out;

    // 8,388,608 threads = 32768 blocks of 256
    rope_v8<<<N8_TOTAL / 256, 256>>>(x, out, pos);
}